// round 3
// baseline (speedup 1.0000x reference)
#include <cuda_runtime.h>
#include <math.h>

// Problem constants
#define BB   8
#define CC   128
#define HH   64
#define WW   64
#define HW   4096           // 64*64
#define OCC  18             // offset conv output channels
#define KK9  9
#define CIKK 1152           // 128*9
#define DT   16             // pixels per deform block
#define PROW 20             // padded sample row stride (floats), 16B aligned
#define NJ   (KK9 * DT)     // 144 sampling points per block
#define SAMP_BYTES (CIKK * PROW * 4)   // 92160

// ---------------- device scratch (no allocations allowed) ----------------
__device__ float g_off1[BB * OCC * HW];
__device__ float g_off2[BB * OCC * HW];
__device__ float g_out1[BB * CC * HW];
__device__ float g_xt  [BB * HW * CC];     // NHWC staging
__device__ float g_wt1 [CIKK * CC];        // transposed deform weights [cik][co]
__device__ float g_wt2 [CIKK * CC];

// ---------------- weight transpose prep: [co][cik] -> [cik][co] ----------------
__global__ void wtrans_kernel(const float* __restrict__ w1,
                              const float* __restrict__ w2)
{
    int cik = blockIdx.x;      // 0..1151
    int co  = threadIdx.x;     // 0..127
    g_wt1[cik * CC + co] = w1[co * CIKK + cik];
    g_wt2[cik * CC + co] = w2[co * CIKK + cik];
}

// ---------------- offset conv: 3x3, pad 1, stride 1, Cout=18 ----------------
__global__ __launch_bounds__(384) void offconv_kernel(
    const float* __restrict__ x, const float* __restrict__ wt,
    const float* __restrict__ bias, float* __restrict__ out)
{
    int bh = blockIdx.x;
    int b = bh >> 6;
    int h = bh & 63;
    int tx = threadIdx.x;           // 0..63 (w)
    int ty = threadIdx.y;           // 0..5
    int tid = ty * 64 + tx;         // 0..383

    __shared__ float xs[3][16][66];     // [ky][ci][w+1 halo]
    __shared__ float ws[16][18][12];    // [ci][oc][kk padded to 12 for v4]

    float acc[3] = {0.f, 0.f, 0.f};
    const float* xb = x + b * CC * HW;

    for (int c0 = 0; c0 < CC; c0 += 16) {
        __syncthreads();
        for (int i = tid; i < 3 * 16 * 66; i += 384) {
            int ky = i / (16 * 66);
            int r  = i % (16 * 66);
            int ci = r / 66;
            int wp = r % 66;
            int iy = h + ky - 1;
            int ix = wp - 1;
            float v = 0.f;
            if (iy >= 0 && iy < HH && ix >= 0 && ix < WW)
                v = xb[(c0 + ci) * HW + iy * WW + ix];
            xs[ky][ci][wp] = v;
        }
        for (int i = tid; i < 16 * 18 * 9; i += 384) {
            int ci = i / 162;
            int r  = i % 162;
            int oc = r / 9;
            int kk = r % 9;
            ws[ci][oc][kk] = wt[oc * CIKK + (c0 + ci) * 9 + kk];
        }
        __syncthreads();

        for (int ci = 0; ci < 16; ci++) {
            float xr[9];
            #pragma unroll
            for (int ky = 0; ky < 3; ky++)
                #pragma unroll
                for (int kx = 0; kx < 3; kx++)
                    xr[ky * 3 + kx] = xs[ky][ci][tx + kx];
            #pragma unroll
            for (int j = 0; j < 3; j++) {
                int oc = ty * 3 + j;
                const float4* wp4 = (const float4*)&ws[ci][oc][0];
                float4 wa = wp4[0];
                float4 wb = wp4[1];
                float  w8 = ws[ci][oc][8];
                acc[j] += wa.x * xr[0] + wa.y * xr[1] + wa.z * xr[2]
                        + wa.w * xr[3] + wb.x * xr[4] + wb.y * xr[5]
                        + wb.z * xr[6] + wb.w * xr[7] + w8 * xr[8];
            }
        }
    }

    #pragma unroll
    for (int j = 0; j < 3; j++) {
        int oc = ty * 3 + j;
        out[((b * OCC + oc) << 12) + h * WW + tx] = acc[j] + bias[oc];
    }
}

// ---------------- NCHW -> NHWC transpose ----------------
__global__ void transpose_kernel(const float* __restrict__ in, float* __restrict__ out)
{
    __shared__ float tile[32][33];
    int b  = blockIdx.z;
    int c0 = blockIdx.y * 32;
    int p0 = blockIdx.x * 32;
    int tx = threadIdx.x, ty = threadIdx.y;   // (32, 8)
    const float* ib = in + b * CC * HW;
    float* ob = out + b * HW * CC;
    #pragma unroll
    for (int k = 0; k < 4; k++) {
        int c = c0 + ty + k * 8;
        tile[ty + k * 8][tx] = ib[c * HW + p0 + tx];
    }
    __syncthreads();
    #pragma unroll
    for (int k = 0; k < 4; k++) {
        int p = p0 + ty + k * 8;
        ob[p * CC + c0 + tx] = tile[tx][ty + k * 8];
    }
}

// ---------------- deform conv (3x3, pad 2, dil 2) + BN (+ residual) + ReLU --
// 256 threads, DT=16 pixels. Thread (c = tid&63, q = tid>>6) computes
// co = 2c, 2c+1 over pixel quad q (4 pixels): 8 accumulators.
// Sample tile in dynamic smem: [cik][PROW] (pixel-major rows, padded).
__global__ __launch_bounds__(256) void deform_kernel(
    const float* __restrict__ xt,      // NHWC input
    const float* __restrict__ off,     // [b][18][hw]
    const float* __restrict__ wtt,     // transposed weights [cik][co]
    const float* __restrict__ gamma, const float* __restrict__ beta,
    const float* __restrict__ mean,  const float* __restrict__ var,
    const float* __restrict__ resid,   // nullptr for stage 1
    float* __restrict__ out)           // NCHW
{
    extern __shared__ float s_samp[];        // CIKK * PROW floats
    __shared__ int   s_y0[NJ], s_x0[NJ];
    __shared__ float s_fy[NJ], s_fx[NJ];

    int bx   = blockIdx.x;
    int b    = bx >> 8;                // 256 blocks per batch
    int pix0 = (bx & 255) << 4;        // 16 pixels per block
    int tid  = threadIdx.x;            // 0..255

    // sampling coordinates: j = kk*DT + t
    if (tid < NJ) {
        int j  = tid;
        int kk = j >> 4;
        int t  = j & 15;
        int pix = pix0 + t;
        int h = pix >> 6;
        int w = pix & 63;
        int ky = kk / 3, kx = kk % 3;
        const float* ob = off + b * OCC * HW;
        float dy = ob[(2 * kk)     * HW + pix];
        float dx = ob[(2 * kk + 1) * HW + pix];
        float ys = (float)(h - 2 + 2 * ky) + dy;
        float xs = (float)(w - 2 + 2 * kx) + dx;
        float y0f = floorf(ys), x0f = floorf(xs);
        s_y0[j] = (int)y0f;
        s_x0[j] = (int)x0f;
        s_fy[j] = ys - y0f;
        s_fx[j] = xs - x0f;
    }
    __syncthreads();

    // gather: lane = channel ci (coalesced NHWC reads), each half-block
    // covers alternating sampling points.
    {
        const float* xb = xt + b * HW * CC;
        int ci = tid & 127;
        int j0 = tid >> 7;             // 0 or 1
        for (int j = j0; j < NJ; j += 2) {
            int   y0 = s_y0[j], x0 = s_x0[j];
            float fy = s_fy[j], fx = s_fx[j];
            int y1 = y0 + 1, x1 = x0 + 1;
            bool y0ok = (y0 >= 0) && (y0 < HH);
            bool y1ok = (y1 >= 0) && (y1 < HH);
            bool x0ok = (x0 >= 0) && (x0 < WW);
            bool x1ok = (x1 >= 0) && (x1 < WW);
            float v00 = (y0ok && x0ok) ? xb[(y0 * WW + x0) * CC + ci] : 0.f;
            float v01 = (y0ok && x1ok) ? xb[(y0 * WW + x1) * CC + ci] : 0.f;
            float v10 = (y1ok && x0ok) ? xb[(y1 * WW + x0) * CC + ci] : 0.f;
            float v11 = (y1ok && x1ok) ? xb[(y1 * WW + x1) * CC + ci] : 0.f;
            float wa = (1.f - fy) * (1.f - fx);
            float wb = (1.f - fy) * fx;
            float wc = fy * (1.f - fx);
            float wd = fy * fx;
            int kk = j >> 4;
            int t  = j & 15;
            s_samp[(ci * KK9 + kk) * PROW + t] =
                wa * v00 + wb * v01 + wc * v10 + wd * v11;
        }
    }
    __syncthreads();

    // compute: thread (c, q): co = 2c, 2c+1 over pixels q*4 .. q*4+3
    int c = tid & 63;
    int q = tid >> 6;
    int qoff = q * 4;

    float a0x = 0.f, a0y = 0.f, a0z = 0.f, a0w = 0.f;
    float a1x = 0.f, a1y = 0.f, a1z = 0.f, a1w = 0.f;

    const float* wp = wtt + 2 * c;         // advance by CC per cik
    const float* sp = s_samp + qoff;
    for (int ci = 0; ci < CC; ci++) {
        #pragma unroll
        for (int kk = 0; kk < KK9; kk++) {
            float2 w2 = *(const float2*)wp;
            wp += CC;
            float4 a = *(const float4*)(sp + (ci * KK9 + kk) * PROW);
            a0x = fmaf(w2.x, a.x, a0x);
            a0y = fmaf(w2.x, a.y, a0y);
            a0z = fmaf(w2.x, a.z, a0z);
            a0w = fmaf(w2.x, a.w, a0w);
            a1x = fmaf(w2.y, a.x, a1x);
            a1y = fmaf(w2.y, a.y, a1y);
            a1z = fmaf(w2.y, a.z, a1z);
            a1w = fmaf(w2.y, a.w, a1w);
        }
    }

    // BN (+residual) + ReLU, NCHW output, vectorized stores
    #pragma unroll
    for (int h = 0; h < 2; h++) {
        int co = 2 * c + h;
        float inv = gamma[co] * rsqrtf(var[co] + 1e-5f);
        float add = beta[co] - mean[co] * inv;
        float4 r;
        if (h == 0) {
            r.x = a0x * inv + add; r.y = a0y * inv + add;
            r.z = a0z * inv + add; r.w = a0w * inv + add;
        } else {
            r.x = a1x * inv + add; r.y = a1y * inv + add;
            r.z = a1z * inv + add; r.w = a1w * inv + add;
        }
        int base = ((b * CC + co) << 12) + pix0 + qoff;
        if (resid) {
            float4 rv = *(const float4*)(resid + base);
            r.x += rv.x; r.y += rv.y; r.z += rv.z; r.w += rv.w;
        }
        r.x = fmaxf(r.x, 0.f); r.y = fmaxf(r.y, 0.f);
        r.z = fmaxf(r.z, 0.f); r.w = fmaxf(r.w, 0.f);
        *(float4*)(out + base) = r;
    }
}

// ---------------- launch ----------------
extern "C" void kernel_launch(void* const* d_in, const int* in_sizes, int n_in,
                              void* d_out, int out_size)
{
    const float* x      = (const float*)d_in[0];
    const float* w_off1 = (const float*)d_in[1];
    const float* b_off1 = (const float*)d_in[2];
    const float* w_dc1  = (const float*)d_in[3];
    const float* g1     = (const float*)d_in[4];
    const float* beta1  = (const float*)d_in[5];
    const float* m1     = (const float*)d_in[6];
    const float* v1     = (const float*)d_in[7];
    const float* w_off2 = (const float*)d_in[8];
    const float* b_off2 = (const float*)d_in[9];
    const float* w_dc2  = (const float*)d_in[10];
    const float* g2     = (const float*)d_in[11];
    const float* beta2  = (const float*)d_in[12];
    const float* m2     = (const float*)d_in[13];
    const float* v2     = (const float*)d_in[14];
    float* out = (float*)d_out;

    float *off1, *off2, *out1, *xt, *wt1, *wt2;
    cudaGetSymbolAddress((void**)&off1, g_off1);
    cudaGetSymbolAddress((void**)&off2, g_off2);
    cudaGetSymbolAddress((void**)&out1, g_out1);
    cudaGetSymbolAddress((void**)&xt,   g_xt);
    cudaGetSymbolAddress((void**)&wt1,  g_wt1);
    cudaGetSymbolAddress((void**)&wt2,  g_wt2);

    static int smem_set = 0;
    if (!smem_set) {
        cudaFuncSetAttribute(deform_kernel,
                             cudaFuncAttributeMaxDynamicSharedMemorySize,
                             SAMP_BYTES);
        smem_set = 1;
    }

    dim3 ocBlk(64, 6);
    dim3 trGrid(HW / 32, CC / 32, BB), trBlk(32, 8);

    wtrans_kernel<<<CIKK, CC>>>(w_dc1, w_dc2);

    // stage 1
    offconv_kernel<<<BB * HH, ocBlk>>>(x, w_off1, b_off1, off1);
    transpose_kernel<<<trGrid, trBlk>>>(x, xt);
    deform_kernel<<<BB * HW / DT, 256, SAMP_BYTES>>>(
        xt, off1, wt1, g1, beta1, m1, v1, nullptr, out1);
    // stage 2
    offconv_kernel<<<BB * HH, ocBlk>>>(out1, w_off2, b_off2, off2);
    transpose_kernel<<<trGrid, trBlk>>>(out1, xt);
    deform_kernel<<<BB * HW / DT, 256, SAMP_BYTES>>>(
        xt, off2, wt2, g2, beta2, m2, v2, x, out);
}

// round 4
// speedup vs baseline: 1.5294x; 1.5294x over previous
#include <cuda_runtime.h>
#include <math.h>

// Problem constants
#define BB   8
#define CC   128
#define HH   64
#define WW   64
#define HW   4096           // 64*64
#define OCC  18             // offset conv output channels
#define KK9  9
#define CIKK 1152           // 128*9
#define DT   8              // pixels per deform block
#define CISTR 76            // padded per-ci stride in sample tile (floats)

// packed f32x2 fma: acc = w * s + acc  (two fp32 lanes per instruction)
#define FMA2(acc, w, s) \
    asm("fma.rn.f32x2 %0, %1, %2, %0;" : "+l"(acc) : "l"(w), "l"(s))

// ---------------- device scratch (no allocations allowed) ----------------
__device__ float g_off1[BB * OCC * HW];
__device__ float g_off2[BB * OCC * HW];
__device__ float g_out1[BB * CC * HW];
__device__ float g_xt  [BB * HW * CC];     // NHWC staging
__device__ float g_wt1 [CIKK * CC];        // transposed deform weights [cik][co]
__device__ float g_wt2 [CIKK * CC];

// ---------------- weight transpose prep: [co][cik] -> [cik][co] ----------------
__global__ void wtrans_kernel(const float* __restrict__ w1,
                              const float* __restrict__ w2)
{
    int cik = blockIdx.x;      // 0..1151
    int co  = threadIdx.x;     // 0..127
    g_wt1[cik * CC + co] = w1[co * CIKK + cik];
    g_wt2[cik * CC + co] = w2[co * CIKK + cik];
}

// ---------------- offset conv: 3x3, pad 1, stride 1, Cout=18 ----------------
__global__ __launch_bounds__(384) void offconv_kernel(
    const float* __restrict__ x, const float* __restrict__ wt,
    const float* __restrict__ bias, float* __restrict__ out)
{
    int bh = blockIdx.x;
    int b = bh >> 6;
    int h = bh & 63;
    int tx = threadIdx.x;           // 0..63 (w)
    int ty = threadIdx.y;           // 0..5
    int tid = ty * 64 + tx;         // 0..383

    __shared__ float xs[3][16][66];     // [ky][ci][w+1 halo]
    __shared__ float ws[16][18][12];    // [ci][oc][kk padded to 12 for v4]

    float acc[3] = {0.f, 0.f, 0.f};
    const float* xb = x + b * CC * HW;

    for (int c0 = 0; c0 < CC; c0 += 16) {
        __syncthreads();
        for (int i = tid; i < 3 * 16 * 66; i += 384) {
            int ky = i / (16 * 66);
            int r  = i % (16 * 66);
            int ci = r / 66;
            int wp = r % 66;
            int iy = h + ky - 1;
            int ix = wp - 1;
            float v = 0.f;
            if (iy >= 0 && iy < HH && ix >= 0 && ix < WW)
                v = xb[(c0 + ci) * HW + iy * WW + ix];
            xs[ky][ci][wp] = v;
        }
        for (int i = tid; i < 16 * 18 * 9; i += 384) {
            int ci = i / 162;
            int r  = i % 162;
            int oc = r / 9;
            int kk = r % 9;
            ws[ci][oc][kk] = wt[oc * CIKK + (c0 + ci) * 9 + kk];
        }
        __syncthreads();

        for (int ci = 0; ci < 16; ci++) {
            float xr[9];
            #pragma unroll
            for (int ky = 0; ky < 3; ky++)
                #pragma unroll
                for (int kx = 0; kx < 3; kx++)
                    xr[ky * 3 + kx] = xs[ky][ci][tx + kx];
            #pragma unroll
            for (int j = 0; j < 3; j++) {
                int oc = ty * 3 + j;
                const float4* wp4 = (const float4*)&ws[ci][oc][0];
                float4 wa = wp4[0];
                float4 wb = wp4[1];
                float  w8 = ws[ci][oc][8];
                acc[j] += wa.x * xr[0] + wa.y * xr[1] + wa.z * xr[2]
                        + wa.w * xr[3] + wb.x * xr[4] + wb.y * xr[5]
                        + wb.z * xr[6] + wb.w * xr[7] + w8 * xr[8];
            }
        }
    }

    #pragma unroll
    for (int j = 0; j < 3; j++) {
        int oc = ty * 3 + j;
        out[((b * OCC + oc) << 12) + h * WW + tx] = acc[j] + bias[oc];
    }
}

// ---------------- NCHW -> NHWC transpose ----------------
__global__ void transpose_kernel(const float* __restrict__ in, float* __restrict__ out)
{
    __shared__ float tile[32][33];
    int b  = blockIdx.z;
    int c0 = blockIdx.y * 32;
    int p0 = blockIdx.x * 32;
    int tx = threadIdx.x, ty = threadIdx.y;   // (32, 8)
    const float* ib = in + b * CC * HW;
    float* ob = out + b * HW * CC;
    #pragma unroll
    for (int k = 0; k < 4; k++) {
        int c = c0 + ty + k * 8;
        tile[ty + k * 8][tx] = ib[c * HW + p0 + tx];
    }
    __syncthreads();
    #pragma unroll
    for (int k = 0; k < 4; k++) {
        int p = p0 + ty + k * 8;
        ob[p * CC + c0 + tx] = tile[tx][ty + k * 8];
    }
}

// ---------------- deform conv (3x3, pad 2, dil 2) + BN (+ residual) + ReLU --
// 64-thread block, DT=8 pixels. Thread t computes co = 2t, 2t+1 over 8 pixels
// using packed f32x2 FMAs (pixel pairs). Gather is branch-free: clamped
// offsets + validity-folded bilinear weights precomputed per sampling point.
__global__ __launch_bounds__(64) void deform_kernel(
    const float* __restrict__ xt,      // NHWC input
    const float* __restrict__ off,     // [b][18][hw]
    const float* __restrict__ wtt,     // transposed weights [cik][co]
    const float* __restrict__ gamma, const float* __restrict__ beta,
    const float* __restrict__ mean,  const float* __restrict__ var,
    const float* __restrict__ resid,   // nullptr for stage 1
    float* __restrict__ out)           // NCHW
{
    int bx   = blockIdx.x;
    int b    = bx >> 9;                // 512 blocks per batch
    int pix0 = (bx & 511) << 3;
    int tid  = threadIdx.x;            // 0..63

    __shared__ float  s_samp[CC * CISTR];   // 38912 B
    __shared__ int4   s_o[72];              // clamped element offsets
    __shared__ float4 s_w[72];              // validity-folded bilinear weights

    // sampling coordinates: j = kk*8 + t
    for (int j = tid; j < 72; j += 64) {
        int kk = j >> 3;
        int t  = j & 7;
        int pix = pix0 + t;
        int h = pix >> 6;
        int w = pix & 63;
        int ky = kk / 3, kx = kk % 3;
        const float* ob = off + b * OCC * HW;
        float dy = ob[(2 * kk)     * HW + pix];
        float dx = ob[(2 * kk + 1) * HW + pix];
        float ys = (float)(h - 2 + 2 * ky) + dy;
        float xs = (float)(w - 2 + 2 * kx) + dx;
        float y0f = floorf(ys), x0f = floorf(xs);
        int y0 = (int)y0f, x0 = (int)x0f;
        int y1 = y0 + 1,   x1 = x0 + 1;
        float fy = ys - y0f, fx = xs - x0f;
        float vy0 = (y0 >= 0 && y0 < HH) ? 1.f : 0.f;
        float vy1 = (y1 >= 0 && y1 < HH) ? 1.f : 0.f;
        float vx0 = (x0 >= 0 && x0 < WW) ? 1.f : 0.f;
        float vx1 = (x1 >= 0 && x1 < WW) ? 1.f : 0.f;
        int iy0 = min(max(y0, 0), HH - 1), iy1 = min(max(y1, 0), HH - 1);
        int ix0 = min(max(x0, 0), WW - 1), ix1 = min(max(x1, 0), WW - 1);
        int4 o;
        o.x = (iy0 * WW + ix0) * CC;
        o.y = (iy0 * WW + ix1) * CC;
        o.z = (iy1 * WW + ix0) * CC;
        o.w = (iy1 * WW + ix1) * CC;
        float4 wv;
        wv.x = (1.f - fy) * (1.f - fx) * vy0 * vx0;
        wv.y = (1.f - fy) * fx         * vy0 * vx1;
        wv.z = fy * (1.f - fx)         * vy1 * vx0;
        wv.w = fy * fx                 * vy1 * vx1;
        s_o[j] = o;
        s_w[j] = wv;
    }
    __syncthreads();

    // gather: lanes = consecutive ci -> coalesced 128B NHWC reads, no branches
    {
        const float* xb = xt + b * HW * CC;
        #pragma unroll 2
        for (int j = 0; j < 72; j++) {
            int4   o  = s_o[j];
            float4 wv = s_w[j];
            #pragma unroll
            for (int half = 0; half < 2; half++) {
                int ci = tid + half * 64;
                float v00 = xb[o.x + ci];
                float v01 = xb[o.y + ci];
                float v10 = xb[o.z + ci];
                float v11 = xb[o.w + ci];
                s_samp[ci * CISTR + j] =
                    wv.x * v00 + wv.y * v01 + wv.z * v10 + wv.w * v11;
            }
        }
    }
    __syncthreads();

    // compute: thread t handles co0 = 2t, co1 = 2t+1 over 8 pixels,
    // packed f32x2 FMAs (4 pixel-pairs per co).
    unsigned long long A0[4], A1[4];
    #pragma unroll
    for (int k = 0; k < 4; k++) { A0[k] = 0ull; A1[k] = 0ull; }

    const float* wp = wtt + 2 * tid;       // advance by CC per cik
    for (int ci = 0; ci < CC; ci++) {
        const float* srow = &s_samp[ci * CISTR];
        #pragma unroll
        for (int kk = 0; kk < KK9; kk++) {
            float2 w2 = *(const float2*)wp;
            wp += CC;
            unsigned long long wxx, wyy;
            asm("mov.b64 %0, {%1, %1};" : "=l"(wxx) : "f"(w2.x));
            asm("mov.b64 %0, {%1, %1};" : "=l"(wyy) : "f"(w2.y));
            ulonglong2 s01 = *(const ulonglong2*)(srow + kk * 8);
            ulonglong2 s23 = *(const ulonglong2*)(srow + kk * 8 + 4);
            FMA2(A0[0], wxx, s01.x);
            FMA2(A0[1], wxx, s01.y);
            FMA2(A0[2], wxx, s23.x);
            FMA2(A0[3], wxx, s23.y);
            FMA2(A1[0], wyy, s01.x);
            FMA2(A1[1], wyy, s01.y);
            FMA2(A1[2], wyy, s23.x);
            FMA2(A1[3], wyy, s23.y);
        }
    }

    // BN (+residual) + ReLU, NCHW output, vectorized stores
    #pragma unroll
    for (int h = 0; h < 2; h++) {
        int co = 2 * tid + h;
        float inv = gamma[co] * rsqrtf(var[co] + 1e-5f);
        float add = beta[co] - mean[co] * inv;
        float p[8];
        #pragma unroll
        for (int k = 0; k < 4; k++) {
            unsigned long long v = h ? A1[k] : A0[k];
            float lo, hi;
            asm("mov.b64 {%0, %1}, %2;" : "=f"(lo), "=f"(hi) : "l"(v));
            p[2 * k]     = lo;
            p[2 * k + 1] = hi;
        }
        int base = ((b * CC + co) << 12) + pix0;
        float4 r0, r1;
        r0.x = p[0] * inv + add;  r0.y = p[1] * inv + add;
        r0.z = p[2] * inv + add;  r0.w = p[3] * inv + add;
        r1.x = p[4] * inv + add;  r1.y = p[5] * inv + add;
        r1.z = p[6] * inv + add;  r1.w = p[7] * inv + add;
        if (resid) {
            const float4* rp = (const float4*)(resid + base);
            float4 q0 = rp[0], q1 = rp[1];
            r0.x += q0.x; r0.y += q0.y; r0.z += q0.z; r0.w += q0.w;
            r1.x += q1.x; r1.y += q1.y; r1.z += q1.z; r1.w += q1.w;
        }
        r0.x = fmaxf(r0.x, 0.f); r0.y = fmaxf(r0.y, 0.f);
        r0.z = fmaxf(r0.z, 0.f); r0.w = fmaxf(r0.w, 0.f);
        r1.x = fmaxf(r1.x, 0.f); r1.y = fmaxf(r1.y, 0.f);
        r1.z = fmaxf(r1.z, 0.f); r1.w = fmaxf(r1.w, 0.f);
        *(float4*)(out + base)     = r0;
        *(float4*)(out + base + 4) = r1;
    }
}

// ---------------- launch ----------------
extern "C" void kernel_launch(void* const* d_in, const int* in_sizes, int n_in,
                              void* d_out, int out_size)
{
    const float* x      = (const float*)d_in[0];
    const float* w_off1 = (const float*)d_in[1];
    const float* b_off1 = (const float*)d_in[2];
    const float* w_dc1  = (const float*)d_in[3];
    const float* g1     = (const float*)d_in[4];
    const float* beta1  = (const float*)d_in[5];
    const float* m1     = (const float*)d_in[6];
    const float* v1     = (const float*)d_in[7];
    const float* w_off2 = (const float*)d_in[8];
    const float* b_off2 = (const float*)d_in[9];
    const float* w_dc2  = (const float*)d_in[10];
    const float* g2     = (const float*)d_in[11];
    const float* beta2  = (const float*)d_in[12];
    const float* m2     = (const float*)d_in[13];
    const float* v2     = (const float*)d_in[14];
    float* out = (float*)d_out;

    float *off1, *off2, *out1, *xt, *wt1, *wt2;
    cudaGetSymbolAddress((void**)&off1, g_off1);
    cudaGetSymbolAddress((void**)&off2, g_off2);
    cudaGetSymbolAddress((void**)&out1, g_out1);
    cudaGetSymbolAddress((void**)&xt,   g_xt);
    cudaGetSymbolAddress((void**)&wt1,  g_wt1);
    cudaGetSymbolAddress((void**)&wt2,  g_wt2);

    dim3 ocBlk(64, 6);
    dim3 trGrid(HW / 32, CC / 32, BB), trBlk(32, 8);

    wtrans_kernel<<<CIKK, CC>>>(w_dc1, w_dc2);

    // stage 1
    offconv_kernel<<<BB * HH, ocBlk>>>(x, w_off1, b_off1, off1);
    transpose_kernel<<<trGrid, trBlk>>>(x, xt);
    deform_kernel<<<BB * HW / DT, 64>>>(xt, off1, wt1, g1, beta1, m1, v1,
                                        nullptr, out1);
    // stage 2
    offconv_kernel<<<BB * HH, ocBlk>>>(out1, w_off2, b_off2, off2);
    transpose_kernel<<<trGrid, trBlk>>>(out1, xt);
    deform_kernel<<<BB * HW / DT, 64>>>(xt, off2, wt2, g2, beta2, m2, v2,
                                        x, out);
}

// round 5
// speedup vs baseline: 1.7022x; 1.1130x over previous
#include <cuda_runtime.h>
#include <math.h>

// Problem constants
#define BB   8
#define CC   128
#define HH   64
#define WW   64
#define HW   4096           // 64*64
#define OCC  18             // offset conv output channels
#define KK9  9
#define CIKK 1152           // 128*9
#define DT   8              // pixels per deform block
#define CISTR 76            // padded per-ci stride in sample tile (floats)
#define CICH 32             // ci channels per chunk

// packed f32x2 fma: acc = w * s + acc  (two fp32 lanes per instruction)
#define FMA2(acc, w, s) \
    asm("fma.rn.f32x2 %0, %1, %2, %0;" : "+l"(acc) : "l"(w), "l"(s))

// ---------------- device scratch (no allocations allowed) ----------------
__device__ float g_off1[BB * OCC * HW];
__device__ float g_off2[BB * OCC * HW];
__device__ float g_out1[BB * CC * HW];
__device__ float g_xt  [BB * HW * CC];     // NHWC staging
__device__ float g_wt1 [CIKK * CC];        // transposed deform weights [cik][co]
__device__ float g_wt2 [CIKK * CC];

// ---------------- weight transpose prep: [co][cik] -> [cik][co] ----------------
__global__ void wtrans_kernel(const float* __restrict__ w1,
                              const float* __restrict__ w2)
{
    int cik = blockIdx.x;      // 0..1151
    int co  = threadIdx.x;     // 0..127
    g_wt1[cik * CC + co] = w1[co * CIKK + cik];
    g_wt2[cik * CC + co] = w2[co * CIKK + cik];
}

// ---------------- offset conv: 3x3, pad 1, stride 1, Cout=18 ----------------
__global__ __launch_bounds__(384) void offconv_kernel(
    const float* __restrict__ x, const float* __restrict__ wt,
    const float* __restrict__ bias, float* __restrict__ out)
{
    int bh = blockIdx.x;
    int b = bh >> 6;
    int h = bh & 63;
    int tx = threadIdx.x;           // 0..63 (w)
    int ty = threadIdx.y;           // 0..5
    int tid = ty * 64 + tx;         // 0..383

    __shared__ float xs[3][16][66];     // [ky][ci][w+1 halo]
    __shared__ float ws[16][18][12];    // [ci][oc][kk padded to 12 for v4]

    float acc[3] = {0.f, 0.f, 0.f};
    const float* xb = x + b * CC * HW;

    for (int c0 = 0; c0 < CC; c0 += 16) {
        __syncthreads();
        for (int i = tid; i < 3 * 16 * 66; i += 384) {
            int ky = i / (16 * 66);
            int r  = i % (16 * 66);
            int ci = r / 66;
            int wp = r % 66;
            int iy = h + ky - 1;
            int ix = wp - 1;
            float v = 0.f;
            if (iy >= 0 && iy < HH && ix >= 0 && ix < WW)
                v = xb[(c0 + ci) * HW + iy * WW + ix];
            xs[ky][ci][wp] = v;
        }
        for (int i = tid; i < 16 * 18 * 9; i += 384) {
            int ci = i / 162;
            int r  = i % 162;
            int oc = r / 9;
            int kk = r % 9;
            ws[ci][oc][kk] = wt[oc * CIKK + (c0 + ci) * 9 + kk];
        }
        __syncthreads();

        for (int ci = 0; ci < 16; ci++) {
            float xr[9];
            #pragma unroll
            for (int ky = 0; ky < 3; ky++)
                #pragma unroll
                for (int kx = 0; kx < 3; kx++)
                    xr[ky * 3 + kx] = xs[ky][ci][tx + kx];
            #pragma unroll
            for (int j = 0; j < 3; j++) {
                int oc = ty * 3 + j;
                const float4* wp4 = (const float4*)&ws[ci][oc][0];
                float4 wa = wp4[0];
                float4 wb = wp4[1];
                float  w8 = ws[ci][oc][8];
                acc[j] += wa.x * xr[0] + wa.y * xr[1] + wa.z * xr[2]
                        + wa.w * xr[3] + wb.x * xr[4] + wb.y * xr[5]
                        + wb.z * xr[6] + wb.w * xr[7] + w8 * xr[8];
            }
        }
    }

    #pragma unroll
    for (int j = 0; j < 3; j++) {
        int oc = ty * 3 + j;
        out[((b * OCC + oc) << 12) + h * WW + tx] = acc[j] + bias[oc];
    }
}

// ---------------- NCHW -> NHWC transpose ----------------
__global__ void transpose_kernel(const float* __restrict__ in, float* __restrict__ out)
{
    __shared__ float tile[32][33];
    int b  = blockIdx.z;
    int c0 = blockIdx.y * 32;
    int p0 = blockIdx.x * 32;
    int tx = threadIdx.x, ty = threadIdx.y;   // (32, 8)
    const float* ib = in + b * CC * HW;
    float* ob = out + b * HW * CC;
    #pragma unroll
    for (int k = 0; k < 4; k++) {
        int c = c0 + ty + k * 8;
        tile[ty + k * 8][tx] = ib[c * HW + p0 + tx];
    }
    __syncthreads();
    #pragma unroll
    for (int k = 0; k < 4; k++) {
        int p = p0 + ty + k * 8;
        ob[p * CC + c0 + tx] = tile[tx][ty + k * 8];
    }
}

// ---------------- deform conv (3x3, pad 2, dil 2) + BN (+ residual) + ReLU --
// 64-thread block, DT=8 pixels, ci chunked (32 channels/chunk) so smem stays
// ~12KB and ~10 blocks/SM coexist (gather of one block overlaps compute of
// others). Thread t computes co = 2t, 2t+1 over 8 pixels via packed f32x2.
__global__ __launch_bounds__(64, 10) void deform_kernel(
    const float* __restrict__ xt,      // NHWC input
    const float* __restrict__ off,     // [b][18][hw]
    const float* __restrict__ wtt,     // transposed weights [cik][co]
    const float* __restrict__ gamma, const float* __restrict__ beta,
    const float* __restrict__ mean,  const float* __restrict__ var,
    const float* __restrict__ resid,   // nullptr for stage 1
    float* __restrict__ out)           // NCHW
{
    int bx   = blockIdx.x;
    int b    = bx >> 9;                // 512 blocks per batch
    int pix0 = (bx & 511) << 3;
    int tid  = threadIdx.x;            // 0..63

    __shared__ float  s_samp[CICH * CISTR];   // 9728 B
    __shared__ int4   s_o[72];                // clamped element offsets
    __shared__ float4 s_w[72];                // validity-folded bilinear weights

    // sampling coordinates: j = kk*8 + t (computed once)
    for (int j = tid; j < 72; j += 64) {
        int kk = j >> 3;
        int t  = j & 7;
        int pix = pix0 + t;
        int h = pix >> 6;
        int w = pix & 63;
        int ky = kk / 3, kx = kk % 3;
        const float* ob = off + b * OCC * HW;
        float dy = ob[(2 * kk)     * HW + pix];
        float dx = ob[(2 * kk + 1) * HW + pix];
        float ys = (float)(h - 2 + 2 * ky) + dy;
        float xs = (float)(w - 2 + 2 * kx) + dx;
        float y0f = floorf(ys), x0f = floorf(xs);
        int y0 = (int)y0f, x0 = (int)x0f;
        int y1 = y0 + 1,   x1 = x0 + 1;
        float fy = ys - y0f, fx = xs - x0f;
        float vy0 = (y0 >= 0 && y0 < HH) ? 1.f : 0.f;
        float vy1 = (y1 >= 0 && y1 < HH) ? 1.f : 0.f;
        float vx0 = (x0 >= 0 && x0 < WW) ? 1.f : 0.f;
        float vx1 = (x1 >= 0 && x1 < WW) ? 1.f : 0.f;
        int iy0 = min(max(y0, 0), HH - 1), iy1 = min(max(y1, 0), HH - 1);
        int ix0 = min(max(x0, 0), WW - 1), ix1 = min(max(x1, 0), WW - 1);
        int4 o;
        o.x = (iy0 * WW + ix0) * CC;
        o.y = (iy0 * WW + ix1) * CC;
        o.z = (iy1 * WW + ix0) * CC;
        o.w = (iy1 * WW + ix1) * CC;
        float4 wv;
        wv.x = (1.f - fy) * (1.f - fx) * vy0 * vx0;
        wv.y = (1.f - fy) * fx         * vy0 * vx1;
        wv.z = fy * (1.f - fx)         * vy1 * vx0;
        wv.w = fy * fx                 * vy1 * vx1;
        s_o[j] = o;
        s_w[j] = wv;
    }

    unsigned long long A0[4], A1[4];
    #pragma unroll
    for (int k = 0; k < 4; k++) { A0[k] = 0ull; A1[k] = 0ull; }

    const float* xb0 = xt + b * HW * CC + (tid & 31);
    int jlane = tid >> 5;              // warp0 -> even j, warp1 -> odd j
    const float* wp = wtt + 2 * tid;   // advance by CC per cik

    for (int c0 = 0; c0 < CC; c0 += CICH) {
        __syncthreads();               // prev compute done / coords ready

        // gather chunk: lane = ci within chunk (coalesced 128B per warp)
        {
            const float* xb = xb0 + c0;
            int cil = tid & 31;
            #pragma unroll 2
            for (int j = jlane; j < 72; j += 2) {
                int4   o  = s_o[j];
                float4 wv = s_w[j];
                float v00 = xb[o.x];
                float v01 = xb[o.y];
                float v10 = xb[o.z];
                float v11 = xb[o.w];
                s_samp[cil * CISTR + j] =
                    wv.x * v00 + wv.y * v01 + wv.z * v10 + wv.w * v11;
            }
        }
        __syncthreads();

        // compute chunk: 32 ci x 9 kk
        for (int cil = 0; cil < CICH; cil++) {
            const float* srow = &s_samp[cil * CISTR];
            #pragma unroll
            for (int kk = 0; kk < KK9; kk++) {
                float2 w2 = *(const float2*)wp;
                wp += CC;
                unsigned long long wxx, wyy;
                asm("mov.b64 %0, {%1, %1};" : "=l"(wxx) : "f"(w2.x));
                asm("mov.b64 %0, {%1, %1};" : "=l"(wyy) : "f"(w2.y));
                ulonglong2 s01 = *(const ulonglong2*)(srow + kk * 8);
                ulonglong2 s23 = *(const ulonglong2*)(srow + kk * 8 + 4);
                FMA2(A0[0], wxx, s01.x);
                FMA2(A0[1], wxx, s01.y);
                FMA2(A0[2], wxx, s23.x);
                FMA2(A0[3], wxx, s23.y);
                FMA2(A1[0], wyy, s01.x);
                FMA2(A1[1], wyy, s01.y);
                FMA2(A1[2], wyy, s23.x);
                FMA2(A1[3], wyy, s23.y);
            }
        }
    }

    // BN (+residual) + ReLU, NCHW output, vectorized stores
    #pragma unroll
    for (int h = 0; h < 2; h++) {
        int co = 2 * tid + h;
        float inv = gamma[co] * rsqrtf(var[co] + 1e-5f);
        float add = beta[co] - mean[co] * inv;
        float p[8];
        #pragma unroll
        for (int k = 0; k < 4; k++) {
            unsigned long long v = h ? A1[k] : A0[k];
            float lo, hi;
            asm("mov.b64 {%0, %1}, %2;" : "=f"(lo), "=f"(hi) : "l"(v));
            p[2 * k]     = lo;
            p[2 * k + 1] = hi;
        }
        int base = ((b * CC + co) << 12) + pix0;
        float4 r0, r1;
        r0.x = p[0] * inv + add;  r0.y = p[1] * inv + add;
        r0.z = p[2] * inv + add;  r0.w = p[3] * inv + add;
        r1.x = p[4] * inv + add;  r1.y = p[5] * inv + add;
        r1.z = p[6] * inv + add;  r1.w = p[7] * inv + add;
        if (resid) {
            const float4* rp = (const float4*)(resid + base);
            float4 q0 = rp[0], q1 = rp[1];
            r0.x += q0.x; r0.y += q0.y; r0.z += q0.z; r0.w += q0.w;
            r1.x += q1.x; r1.y += q1.y; r1.z += q1.z; r1.w += q1.w;
        }
        r0.x = fmaxf(r0.x, 0.f); r0.y = fmaxf(r0.y, 0.f);
        r0.z = fmaxf(r0.z, 0.f); r0.w = fmaxf(r0.w, 0.f);
        r1.x = fmaxf(r1.x, 0.f); r1.y = fmaxf(r1.y, 0.f);
        r1.z = fmaxf(r1.z, 0.f); r1.w = fmaxf(r1.w, 0.f);
        *(float4*)(out + base)     = r0;
        *(float4*)(out + base + 4) = r1;
    }
}

// ---------------- launch ----------------
extern "C" void kernel_launch(void* const* d_in, const int* in_sizes, int n_in,
                              void* d_out, int out_size)
{
    const float* x      = (const float*)d_in[0];
    const float* w_off1 = (const float*)d_in[1];
    const float* b_off1 = (const float*)d_in[2];
    const float* w_dc1  = (const float*)d_in[3];
    const float* g1     = (const float*)d_in[4];
    const float* beta1  = (const float*)d_in[5];
    const float* m1     = (const float*)d_in[6];
    const float* v1     = (const float*)d_in[7];
    const float* w_off2 = (const float*)d_in[8];
    const float* b_off2 = (const float*)d_in[9];
    const float* w_dc2  = (const float*)d_in[10];
    const float* g2     = (const float*)d_in[11];
    const float* beta2  = (const float*)d_in[12];
    const float* m2     = (const float*)d_in[13];
    const float* v2     = (const float*)d_in[14];
    float* out = (float*)d_out;

    float *off1, *off2, *out1, *xt, *wt1, *wt2;
    cudaGetSymbolAddress((void**)&off1, g_off1);
    cudaGetSymbolAddress((void**)&off2, g_off2);
    cudaGetSymbolAddress((void**)&out1, g_out1);
    cudaGetSymbolAddress((void**)&xt,   g_xt);
    cudaGetSymbolAddress((void**)&wt1,  g_wt1);
    cudaGetSymbolAddress((void**)&wt2,  g_wt2);

    dim3 ocBlk(64, 6);
    dim3 trGrid(HW / 32, CC / 32, BB), trBlk(32, 8);

    wtrans_kernel<<<CIKK, CC>>>(w_dc1, w_dc2);

    // stage 1
    offconv_kernel<<<BB * HH, ocBlk>>>(x, w_off1, b_off1, off1);
    transpose_kernel<<<trGrid, trBlk>>>(x, xt);
    deform_kernel<<<BB * HW / DT, 64>>>(xt, off1, wt1, g1, beta1, m1, v1,
                                        nullptr, out1);
    // stage 2
    offconv_kernel<<<BB * HH, ocBlk>>>(out1, w_off2, b_off2, off2);
    transpose_kernel<<<trGrid, trBlk>>>(out1, xt);
    deform_kernel<<<BB * HW / DT, 64>>>(xt, off2, wt2, g2, beta2, m2, v2,
                                        x, out);
}